// round 5
// baseline (speedup 1.0000x reference)
#include <cuda_runtime.h>
#include <cstdint>
#include <math.h>
#include <mma.h>

using namespace nvcuda;

// Problem constants
#define BB   8
#define TT   2048
#define ROWS (BB * TT)      // 16384
#define DIN  64
#define DM   256
#define DI   512
#define NST  16
#define RR   16
#define DOUT 128
#define DBCN 48             // R + 2N
#define LAY  2

// ---------------------------------------------------------------------------
// Scratch (static device globals)
// ---------------------------------------------------------------------------
__device__ float g_h  [ROWS * DM];
__device__ float g_xz [ROWS * 2 * DI];
__device__ float g_xc [ROWS * DI];
__device__ float g_dbc[ROWS * DBCN];
__device__ float g_dt [ROWS * DI];
__device__ float g_y  [ROWS * DI];
// tf32-truncated copies of GEMM B-operands (+x)
#define W_IN_OFF  0
#define WIN_OFF   (W_IN_OFF + DIN * DM)
#define WX_OFF    (WIN_OFF + LAY * DM * 2 * DI)
#define WOUT_OFF  (WX_OFF + LAY * DI * DBCN)
#define WT_TOTAL  (WOUT_OFF + LAY * DI * DM)
__device__ float g_wt [WT_TOTAL];
__device__ float g_xtf[ROWS * DIN];

// ---------------------------------------------------------------------------
// tf32 truncation helper kernel (round-to-nearest, 10-bit mantissa)
// ---------------------------------------------------------------------------
__global__ void tf32_cvt(const float* __restrict__ src, float* __restrict__ dst, int n)
{
    int i = blockIdx.x * blockDim.x + threadIdx.x;
    if (i < n) dst[i] = wmma::__float_to_tf32(src[i]);
}

// ---------------------------------------------------------------------------
// cp.async helpers
// ---------------------------------------------------------------------------
__device__ __forceinline__ void cp16(unsigned int smem_addr, const float* gptr)
{
    asm volatile("cp.async.cg.shared.global [%0], [%1], 16;\n"
                 :: "r"(smem_addr), "l"(gptr));
}
__device__ __forceinline__ void cp_commit()
{
    asm volatile("cp.async.commit_group;\n");
}
template<int N>
__device__ __forceinline__ void cp_wait()
{
    asm volatile("cp.async.wait_group %0;\n" :: "n"(N));
}

// ---------------------------------------------------------------------------
// TF32 tensor-core GEMM, 4-stage cp.async pipeline.
// BM=128, BK=16. 256 threads = 8 warps, warp grid WM x (8/WM).
// All inputs must already be tf32-truncated. Requires M%128==0, N%BN==0,
// K%16==0 (all uses satisfy this exactly -> no guards).
// ---------------------------------------------------------------------------
template<int BN, int WM>
__global__ __launch_bounds__(256, 2) void tgemm(
    const float* __restrict__ A, const float* __restrict__ B,
    const float* __restrict__ bias, float* __restrict__ C,
    int M, int N, int K, int trunc_out)
{
    constexpr int BM = 128, BK = 16, STAGES = 4;
    constexpr int LDA = BK + 4;
    constexpr int LDB = BN + 4;
    constexpr int ASZ = BM * LDA;
    constexpr int BSZ = BK * LDB;
    constexpr int WNW = 8 / WM;              // warps along N
    constexpr int AM  = BM / (WM * 16);      // a-fragments per warp
    constexpr int NF  = BN / (WNW * 16);     // b-fragments per warp
    constexpr int NB4 = BN / 4;              // float4 per B row
    constexpr int BCH = BK * BN / 4;         // B float4 chunks per stage

    extern __shared__ float smem[];
    float* As = smem;
    float* Bs = smem + STAGES * ASZ;

    const int tid  = threadIdx.x;
    const int lane = tid & 31;
    const int wid  = tid >> 5;
    const int wm   = wid % WM;
    const int wn   = wid / WM;
    const int brow = blockIdx.y * BM;
    const int bcol = blockIdx.x * BN;

    wmma::fragment<wmma::accumulator, 16, 16, 8, float> acc[AM][NF];
#pragma unroll
    for (int i = 0; i < AM; i++)
#pragma unroll
        for (int j = 0; j < NF; j++)
            wmma::fill_fragment(acc[i][j], 0.f);

    // A: 512 float4 chunks per stage -> 2 per thread
    const int ar0 = tid >> 2;
    const int ar1 = (tid + 256) >> 2;
    const int ac  = (tid & 3) * 4;

    auto loadStage = [&](int st, int k0) {
        unsigned int abase = (unsigned int)__cvta_generic_to_shared(As + st * ASZ);
        cp16(abase + (unsigned int)(ar0 * LDA + ac) * 4,
             &A[(size_t)(brow + ar0) * K + k0 + ac]);
        cp16(abase + (unsigned int)(ar1 * LDA + ac) * 4,
             &A[(size_t)(brow + ar1) * K + k0 + ac]);
        unsigned int bbase = (unsigned int)__cvta_generic_to_shared(Bs + st * BSZ);
#pragma unroll
        for (int u = 0; u < (BCH + 255) / 256; u++) {
            int i = tid + 256 * u;
            if ((BCH % 256 == 0) || (i < BCH)) {
                int r = i / NB4, c = (i % NB4) * 4;
                cp16(bbase + (unsigned int)(r * LDB + c) * 4,
                     &B[(size_t)(k0 + r) * N + bcol + c]);
            }
        }
    };

    const int ktiles = K / BK;

    // prologue: STAGES-1 stages in flight
#pragma unroll
    for (int s = 0; s < STAGES - 1; s++) {
        if (s < ktiles) loadStage(s, s * BK);
        cp_commit();
    }

    for (int it = 0; it < ktiles; it++) {
        cp_wait<STAGES - 2>();
        __syncthreads();

        const int st = it % STAGES;
        const float* a0 = As + st * ASZ;
        const float* b0 = Bs + st * BSZ;
#pragma unroll
        for (int kk = 0; kk < BK; kk += 8) {
            wmma::fragment<wmma::matrix_a, 16, 16, 8, wmma::precision::tf32,
                           wmma::row_major> af[AM];
            wmma::fragment<wmma::matrix_b, 16, 16, 8, wmma::precision::tf32,
                           wmma::row_major> bf[NF];
#pragma unroll
            for (int i = 0; i < AM; i++)
                wmma::load_matrix_sync(af[i],
                    a0 + (wm * AM * 16 + i * 16) * LDA + kk, LDA);
#pragma unroll
            for (int j = 0; j < NF; j++)
                wmma::load_matrix_sync(bf[j],
                    b0 + kk * LDB + wn * NF * 16 + j * 16, LDB);
#pragma unroll
            for (int i = 0; i < AM; i++)
#pragma unroll
                for (int j = 0; j < NF; j++)
                    wmma::mma_sync(acc[i][j], af[i], bf[j], acc[i][j]);
        }

        const int nf = it + STAGES - 1;
        if (nf < ktiles) loadStage(nf % STAGES, nf * BK);
        cp_commit();
    }

    cp_wait<0>();
    __syncthreads();

    // epilogue: stage fragments through smem (alias over stage buffers)
    float* Ep = smem + wid * 256;
    const int er = lane >> 1;
    const int ec = (lane & 1) * 8;
#pragma unroll
    for (int i = 0; i < AM; i++) {
#pragma unroll
        for (int j = 0; j < NF; j++) {
            wmma::store_matrix_sync(Ep, acc[i][j], 16, wmma::mem_row_major);
            __syncwarp();
            int gr = brow + wm * AM * 16 + i * 16 + er;
            int gc = bcol + wn * NF * 16 + j * 16 + ec;
            float v[8];
#pragma unroll
            for (int q = 0; q < 8; q++) {
                float t = Ep[er * 16 + ec + q] + (bias ? bias[gc + q] : 0.f);
                v[q] = trunc_out ? wmma::__float_to_tf32(t) : t;
            }
            *(float4*)&C[(size_t)gr * N + gc]     = make_float4(v[0], v[1], v[2], v[3]);
            *(float4*)&C[(size_t)gr * N + gc + 4] = make_float4(v[4], v[5], v[6], v[7]);
            __syncwarp();
        }
    }
}

// ---------------------------------------------------------------------------
// Depthwise causal conv (K=4) + SiLU -> tf32-truncated xc
// ---------------------------------------------------------------------------
__global__ void conv_silu(const float* __restrict__ cw,
                          const float* __restrict__ cb)
{
    int idx = blockIdx.x * blockDim.x + threadIdx.x;
    if (idx >= ROWS * DI) return;
    int d   = idx & (DI - 1);
    int row = idx >> 9;
    int t   = row & (TT - 1);

    const float* xi = g_xz + (size_t)row * (2 * DI) + d;
    float w0 = cw[d * 4 + 0], w1 = cw[d * 4 + 1];
    float w2 = cw[d * 4 + 2], w3 = cw[d * 4 + 3];

    float acc = cb[d] + w3 * xi[0];
    if (t >= 1) acc += w2 * xi[-(2 * DI)];
    if (t >= 2) acc += w1 * xi[-(4 * DI)];
    if (t >= 3) acc += w0 * xi[-(6 * DI)];

    float s = __fdividef(acc, 1.f + __expf(-acc));
    g_xc[idx] = wmma::__float_to_tf32(s);
}

// ---------------------------------------------------------------------------
// dt = softplus(dbc[:, :R] @ Wdt + bdt)
// ---------------------------------------------------------------------------
__global__ void dt_softplus(const float* __restrict__ Wdt,
                            const float* __restrict__ bdt)
{
    int idx = blockIdx.x * blockDim.x + threadIdx.x;
    if (idx >= ROWS * DI) return;
    int d   = idx & (DI - 1);
    int row = idx >> 9;

    const float* db = g_dbc + (size_t)row * DBCN;
    float acc = bdt[d];
#pragma unroll
    for (int r = 0; r < RR; r++)
        acc += db[r] * Wdt[r * DI + d];

    g_dt[idx] = (acc > 20.f) ? acc : log1pf(__expf(acc));
}

// ---------------------------------------------------------------------------
// Selective scan fused with gating. 4 threads/(b,d), 4 states each.
// Writes tf32-truncated y (Wout GEMM A-operand).
// ---------------------------------------------------------------------------
#define SCH 16
__global__ __launch_bounds__(128) void ssm_scan_fused(
    const float* __restrict__ A_log_l, const float* __restrict__ Dp_l)
{
    __shared__ __align__(16) float s_dt[2][SCH][32];
    __shared__ __align__(16) float s_x [2][SCH][32];
    __shared__ __align__(16) float s_z [2][SCH][32];
    __shared__ __align__(16) float s_bc[2][SCH][32];

    const int b   = blockIdx.x >> 4;
    const int dg  = blockIdx.x & 15;
    const int d0  = dg * 32;
    const int tid = threadIdx.x;
    const int q   = tid & 3;
    const int dl  = tid >> 2;
    const int d   = d0 + dl;

    const int tl  = tid >> 3;
    const int seg = tid & 7;

    float a[4];
#pragma unroll
    for (int j = 0; j < 4; j++)
        a[j] = -__expf(A_log_l[d * NST + q * 4 + j]);
    const float dp = Dp_l[d];

    const size_t rb = (size_t)b * TT;

    float h0 = 0.f, h1 = 0.f, h2 = 0.f, h3 = 0.f;

    {
        size_t row = rb + tl;
        *(float4*)&s_dt[0][tl][seg * 4] = *(const float4*)&g_dt [row * DI + d0 + seg * 4];
        *(float4*)&s_x [0][tl][seg * 4] = *(const float4*)&g_xc [row * DI + d0 + seg * 4];
        *(float4*)&s_z [0][tl][seg * 4] = *(const float4*)&g_xz [row * (2 * DI) + DI + d0 + seg * 4];
        *(float4*)&s_bc[0][tl][seg * 4] = *(const float4*)&g_dbc[row * DBCN + RR + seg * 4];
    }
    __syncthreads();

    int buf = 0;
    const int NC = TT / SCH;
    for (int c = 0; c < NC; c++) {
        float4 vdt, vx, vz, vbc;
        const bool more = (c + 1 < NC);
        if (more) {
            size_t row = rb + (size_t)(c + 1) * SCH + tl;
            vdt = *(const float4*)&g_dt [row * DI + d0 + seg * 4];
            vx  = *(const float4*)&g_xc [row * DI + d0 + seg * 4];
            vz  = *(const float4*)&g_xz [row * (2 * DI) + DI + d0 + seg * 4];
            vbc = *(const float4*)&g_dbc[row * DBCN + RR + seg * 4];
        }

#pragma unroll
        for (int it = 0; it < SCH; it++) {
            float dt = s_dt[buf][it][dl];
            float x  = s_x [buf][it][dl];
            float4 Bv = *(const float4*)&s_bc[buf][it][q * 4];
            float4 Cv = *(const float4*)&s_bc[buf][it][16 + q * 4];
            float z  = s_z [buf][it][dl];

            float dtx = dt * x;
            h0 = __expf(dt * a[0]) * h0 + dtx * Bv.x;
            h1 = __expf(dt * a[1]) * h1 + dtx * Bv.y;
            h2 = __expf(dt * a[2]) * h2 + dtx * Bv.z;
            h3 = __expf(dt * a[3]) * h3 + dtx * Bv.w;

            float pv = h0 * Cv.x + h1 * Cv.y + h2 * Cv.z + h3 * Cv.w;
            pv += __shfl_xor_sync(0xffffffffu, pv, 1);
            pv += __shfl_xor_sync(0xffffffffu, pv, 2);

            if (q == 0) {
                float sz = __fdividef(z, 1.f + __expf(-z));
                size_t row = rb + (size_t)c * SCH + it;
                g_y[row * DI + d] = wmma::__float_to_tf32((pv + dp * x) * sz);
            }
        }

        if (more) {
            *(float4*)&s_dt[buf ^ 1][tl][seg * 4] = vdt;
            *(float4*)&s_x [buf ^ 1][tl][seg * 4] = vx;
            *(float4*)&s_z [buf ^ 1][tl][seg * 4] = vz;
            *(float4*)&s_bc[buf ^ 1][tl][seg * 4] = vbc;
        }
        __syncthreads();
        buf ^= 1;
    }
}

// ---------------------------------------------------------------------------
// Final: mean over T, then @ W_out_proj + b_out_proj
// ---------------------------------------------------------------------------
__global__ void mean_proj(const float* __restrict__ Wop,
                          const float* __restrict__ bop,
                          float* __restrict__ out)
{
    __shared__ float hm[DM];
    int b = blockIdx.x;
    int c = threadIdx.x;

    float s = 0.f;
    const float* hp = g_h + (size_t)b * TT * DM + c;
    for (int t = 0; t < TT; t++)
        s += hp[(size_t)t * DM];
    hm[c] = s * (1.f / (float)TT);
    __syncthreads();

    if (c < DOUT) {
        float acc = bop[c];
#pragma unroll 4
        for (int k = 0; k < DM; k++)
            acc += hm[k] * Wop[k * DOUT + c];
        out[b * DOUT + c] = acc;
    }
}

// ---------------------------------------------------------------------------
// Orchestration
// ---------------------------------------------------------------------------
static constexpr int SMEM_T(int BN)
{
    return 4 * (128 * 20 + 16 * (BN + 4)) * 4;   // STAGES*(ASZ+BSZ)*4B
}

extern "C" void kernel_launch(void* const* d_in, const int* in_sizes, int n_in,
                              void* d_out, int out_size)
{
    const float* x        = (const float*)d_in[0];
    const float* W_in     = (const float*)d_in[1];
    const float* b_in     = (const float*)d_in[2];
    const float* Win      = (const float*)d_in[3];
    const float* bin_     = (const float*)d_in[4];
    const float* conv_w   = (const float*)d_in[5];
    const float* conv_b   = (const float*)d_in[6];
    const float* Wx       = (const float*)d_in[7];
    const float* Wdt      = (const float*)d_in[8];
    const float* bdt      = (const float*)d_in[9];
    const float* A_log    = (const float*)d_in[10];
    const float* Dp       = (const float*)d_in[11];
    const float* Wout     = (const float*)d_in[12];
    const float* W_op     = (const float*)d_in[13];
    const float* b_op     = (const float*)d_in[14];
    float* out = (float*)d_out;

    float *hbuf, *xzbuf, *xcbuf, *dbcbuf, *ybuf, *wt, *xtf;
    cudaGetSymbolAddress((void**)&hbuf,   g_h);
    cudaGetSymbolAddress((void**)&xzbuf,  g_xz);
    cudaGetSymbolAddress((void**)&xcbuf,  g_xc);
    cudaGetSymbolAddress((void**)&dbcbuf, g_dbc);
    cudaGetSymbolAddress((void**)&ybuf,   g_y);
    cudaGetSymbolAddress((void**)&wt,     g_wt);
    cudaGetSymbolAddress((void**)&xtf,    g_xtf);

    constexpr int SM128 = SMEM_T(128);
    constexpr int SM48  = SMEM_T(48);
    cudaFuncSetAttribute(tgemm<128, 4>, cudaFuncAttributeMaxDynamicSharedMemorySize, SM128);
    cudaFuncSetAttribute(tgemm<48, 8>,  cudaFuncAttributeMaxDynamicSharedMemorySize, SM48);

    // --- pre-truncate GEMM operands to tf32 ---
    auto cvt = [&](const float* src, float* dst, int n) {
        tf32_cvt<<<(n + 255) / 256, 256>>>(src, dst, n);
    };
    cvt(W_in, wt + W_IN_OFF, DIN * DM);
    cvt(Win,  wt + WIN_OFF,  LAY * DM * 2 * DI);
    cvt(Wx,   wt + WX_OFF,   LAY * DI * DBCN);
    cvt(Wout, wt + WOUT_OFF, LAY * DI * DM);
    cvt(x,    xtf,           ROWS * DIN);

    const int EW_BLOCKS = (ROWS * DI + 255) / 256;

    // in_proj: h = x @ W_in + b_in  (truncate output: it's the next GEMM's A)
    {
        dim3 g(DM / 128, ROWS / 128);
        tgemm<128, 4><<<g, 256, SM128>>>(xtf, wt + W_IN_OFF, b_in, hbuf,
                                         ROWS, DM, DIN, 1);
    }

    for (int l = 0; l < LAY; l++) {
        const float* Win_l  = wt + WIN_OFF  + (size_t)l * DM * 2 * DI;
        const float* bin_l  = bin_   + (size_t)l * 2 * DI;
        const float* cw_l   = conv_w + (size_t)l * DI * 4;
        const float* cb_l   = conv_b + (size_t)l * DI;
        const float* Wx_l   = wt + WX_OFF   + (size_t)l * DI * DBCN;
        const float* Wdt_l  = Wdt    + (size_t)l * RR * DI;
        const float* bdt_l  = bdt    + (size_t)l * DI;
        const float* Alog_l = A_log  + (size_t)l * DI * NST;
        const float* Dp_l   = Dp     + (size_t)l * DI;
        const float* Wout_l = wt + WOUT_OFF + (size_t)l * DI * DM;

        // xz = h @ Win + bin  (fp32 out: feeds conv + scan z)
        {
            dim3 g((2 * DI) / 128, ROWS / 128);
            tgemm<128, 4><<<g, 256, SM128>>>(hbuf, Win_l, bin_l, xzbuf,
                                             ROWS, 2 * DI, DM, 0);
        }
        // xc = tf32(silu(conv(xi)))
        conv_silu<<<EW_BLOCKS, 256>>>(cw_l, cb_l);
        // dbc = xc @ Wx  (fp32 out)
        {
            dim3 g(1, ROWS / 128);
            tgemm<48, 8><<<g, 256, SM48>>>(xcbuf, Wx_l, nullptr, dbcbuf,
                                           ROWS, DBCN, DI, 0);
        }
        // dt = softplus(dbc[:, :R] @ Wdt + bdt)
        dt_softplus<<<EW_BLOCKS, 256>>>(Wdt_l, bdt_l);
        // scan + gating -> tf32(y)
        ssm_scan_fused<<<BB * (DI / 32), 128>>>(Alog_l, Dp_l);
        // h = y @ Wout  (truncate: feeds next xz GEMM)
        {
            dim3 g(DM / 128, ROWS / 128);
            tgemm<128, 4><<<g, 256, SM128>>>(ybuf, Wout_l, nullptr, hbuf,
                                             ROWS, DM, DI, 1);
        }
    }

    mean_proj<<<BB, DM>>>(W_op, b_op, out);
}

// round 6
// speedup vs baseline: 1.0515x; 1.0515x over previous
#include <cuda_runtime.h>
#include <cstdint>
#include <math.h>
#include <mma.h>

using namespace nvcuda;

// Problem constants
#define BB   8
#define TT   2048
#define ROWS (BB * TT)      // 16384
#define DIN  64
#define DM   256
#define DI   512
#define NST  16
#define RR   16
#define DOUT 128
#define DBCN 48             // R + 2N
#define LAY  2

// ---------------------------------------------------------------------------
// Scratch (static device globals)
// ---------------------------------------------------------------------------
__device__ float g_h  [ROWS * DM];
__device__ float g_xz [ROWS * 2 * DI];
__device__ float g_xc [ROWS * DI];
__device__ float g_dbc[ROWS * DBCN];
__device__ float g_y  [ROWS * DI];
__device__ float g_part[BB * 32 * DM];
// tf32-truncated copies of GEMM B-operands (+x)
#define W_IN_OFF  0
#define WIN_OFF   (W_IN_OFF + DIN * DM)
#define WX_OFF    (WIN_OFF + LAY * DM * 2 * DI)
#define WOUT_OFF  (WX_OFF + LAY * DI * DBCN)
#define WT_TOTAL  (WOUT_OFF + LAY * DI * DM)
__device__ float g_wt [WT_TOTAL];
__device__ float g_xtf[ROWS * DIN];

// ---------------------------------------------------------------------------
// Batched tf32 truncation (single launch for all operands)
// ---------------------------------------------------------------------------
struct CvtJob  { const float* src; float* dst; int n; };
struct CvtJobs { CvtJob j[5]; };

__global__ void tf32_cvt_multi(CvtJobs jobs, int total)
{
    int i = blockIdx.x * blockDim.x + threadIdx.x;
    if (i >= total) return;
#pragma unroll
    for (int k = 0; k < 5; k++) {
        if (i < jobs.j[k].n) {
            jobs.j[k].dst[i] = wmma::__float_to_tf32(jobs.j[k].src[i]);
            return;
        }
        i -= jobs.j[k].n;
    }
}

// ---------------------------------------------------------------------------
// cp.async helpers
// ---------------------------------------------------------------------------
__device__ __forceinline__ void cp16(unsigned int smem_addr, const float* gptr)
{
    asm volatile("cp.async.cg.shared.global [%0], [%1], 16;\n"
                 :: "r"(smem_addr), "l"(gptr));
}
__device__ __forceinline__ void cp_commit()
{
    asm volatile("cp.async.commit_group;\n");
}
template<int N>
__device__ __forceinline__ void cp_wait()
{
    asm volatile("cp.async.wait_group %0;\n" :: "n"(N));
}

// ---------------------------------------------------------------------------
// TF32 tensor-core GEMM, 4-stage cp.async pipeline (unchanged from R5).
// ---------------------------------------------------------------------------
template<int BN, int WM>
__global__ __launch_bounds__(256, 2) void tgemm(
    const float* __restrict__ A, const float* __restrict__ B,
    const float* __restrict__ bias, float* __restrict__ C,
    int M, int N, int K, int trunc_out)
{
    constexpr int BM = 128, BK = 16, STAGES = 4;
    constexpr int LDA = BK + 4;
    constexpr int LDB = BN + 4;
    constexpr int ASZ = BM * LDA;
    constexpr int BSZ = BK * LDB;
    constexpr int WNW = 8 / WM;
    constexpr int AM  = BM / (WM * 16);
    constexpr int NF  = BN / (WNW * 16);
    constexpr int NB4 = BN / 4;
    constexpr int BCH = BK * BN / 4;

    extern __shared__ float smem[];
    float* As = smem;
    float* Bs = smem + STAGES * ASZ;

    const int tid  = threadIdx.x;
    const int lane = tid & 31;
    const int wid  = tid >> 5;
    const int wm   = wid % WM;
    const int wn   = wid / WM;
    const int brow = blockIdx.y * BM;
    const int bcol = blockIdx.x * BN;

    wmma::fragment<wmma::accumulator, 16, 16, 8, float> acc[AM][NF];
#pragma unroll
    for (int i = 0; i < AM; i++)
#pragma unroll
        for (int j = 0; j < NF; j++)
            wmma::fill_fragment(acc[i][j], 0.f);

    const int ar0 = tid >> 2;
    const int ar1 = (tid + 256) >> 2;
    const int ac  = (tid & 3) * 4;

    auto loadStage = [&](int st, int k0) {
        unsigned int abase = (unsigned int)__cvta_generic_to_shared(As + st * ASZ);
        cp16(abase + (unsigned int)(ar0 * LDA + ac) * 4,
             &A[(size_t)(brow + ar0) * K + k0 + ac]);
        cp16(abase + (unsigned int)(ar1 * LDA + ac) * 4,
             &A[(size_t)(brow + ar1) * K + k0 + ac]);
        unsigned int bbase = (unsigned int)__cvta_generic_to_shared(Bs + st * BSZ);
#pragma unroll
        for (int u = 0; u < (BCH + 255) / 256; u++) {
            int i = tid + 256 * u;
            if ((BCH % 256 == 0) || (i < BCH)) {
                int r = i / NB4, c = (i % NB4) * 4;
                cp16(bbase + (unsigned int)(r * LDB + c) * 4,
                     &B[(size_t)(k0 + r) * N + bcol + c]);
            }
        }
    };

    const int ktiles = K / BK;

#pragma unroll
    for (int s = 0; s < STAGES - 1; s++) {
        if (s < ktiles) loadStage(s, s * BK);
        cp_commit();
    }

    for (int it = 0; it < ktiles; it++) {
        cp_wait<STAGES - 2>();
        __syncthreads();

        const int st = it % STAGES;
        const float* a0 = As + st * ASZ;
        const float* b0 = Bs + st * BSZ;
#pragma unroll
        for (int kk = 0; kk < BK; kk += 8) {
            wmma::fragment<wmma::matrix_a, 16, 16, 8, wmma::precision::tf32,
                           wmma::row_major> af[AM];
            wmma::fragment<wmma::matrix_b, 16, 16, 8, wmma::precision::tf32,
                           wmma::row_major> bf[NF];
#pragma unroll
            for (int i = 0; i < AM; i++)
                wmma::load_matrix_sync(af[i],
                    a0 + (wm * AM * 16 + i * 16) * LDA + kk, LDA);
#pragma unroll
            for (int j = 0; j < NF; j++)
                wmma::load_matrix_sync(bf[j],
                    b0 + kk * LDB + wn * NF * 16 + j * 16, LDB);
#pragma unroll
            for (int i = 0; i < AM; i++)
#pragma unroll
                for (int j = 0; j < NF; j++)
                    wmma::mma_sync(acc[i][j], af[i], bf[j], acc[i][j]);
        }

        const int nf = it + STAGES - 1;
        if (nf < ktiles) loadStage(nf % STAGES, nf * BK);
        cp_commit();
    }

    cp_wait<0>();
    __syncthreads();

    float* Ep = smem + wid * 256;
    const int er = lane >> 1;
    const int ec = (lane & 1) * 8;
#pragma unroll
    for (int i = 0; i < AM; i++) {
#pragma unroll
        for (int j = 0; j < NF; j++) {
            wmma::store_matrix_sync(Ep, acc[i][j], 16, wmma::mem_row_major);
            __syncwarp();
            int gr = brow + wm * AM * 16 + i * 16 + er;
            int gc = bcol + wn * NF * 16 + j * 16 + ec;
            float v[8];
#pragma unroll
            for (int q = 0; q < 8; q++) {
                float t = Ep[er * 16 + ec + q] + (bias ? bias[gc + q] : 0.f);
                v[q] = trunc_out ? wmma::__float_to_tf32(t) : t;
            }
            *(float4*)&C[(size_t)gr * N + gc]     = make_float4(v[0], v[1], v[2], v[3]);
            *(float4*)&C[(size_t)gr * N + gc + 4] = make_float4(v[4], v[5], v[6], v[7]);
            __syncwarp();
        }
    }
}

// ---------------------------------------------------------------------------
// Depthwise causal conv (K=4) + SiLU -> tf32-truncated xc
// ---------------------------------------------------------------------------
__global__ void conv_silu(const float* __restrict__ cw,
                          const float* __restrict__ cb)
{
    int idx = blockIdx.x * blockDim.x + threadIdx.x;
    if (idx >= ROWS * DI) return;
    int d   = idx & (DI - 1);
    int row = idx >> 9;
    int t   = row & (TT - 1);

    const float* xi = g_xz + (size_t)row * (2 * DI) + d;
    float w0 = cw[d * 4 + 0], w1 = cw[d * 4 + 1];
    float w2 = cw[d * 4 + 2], w3 = cw[d * 4 + 3];

    float acc = cb[d] + w3 * xi[0];
    if (t >= 1) acc += w2 * xi[-(2 * DI)];
    if (t >= 2) acc += w1 * xi[-(4 * DI)];
    if (t >= 3) acc += w0 * xi[-(6 * DI)];

    float s = __fdividef(acc, 1.f + __expf(-acc));
    g_xc[idx] = wmma::__float_to_tf32(s);
}

// ---------------------------------------------------------------------------
// Selective scan fused with dt-softplus AND gating.
// 4 threads/(b,d), 4 states each. Block = 128 thr = 32 d-lanes.
// dt computed in-kernel from full dbc rows (staged in smem) + Wdt tile.
// Writes tf32-truncated y.
// ---------------------------------------------------------------------------
#define SCH 16
__global__ __launch_bounds__(128) void ssm_scan_fused(
    const float* __restrict__ A_log_l, const float* __restrict__ Dp_l,
    const float* __restrict__ Wdt_l,   const float* __restrict__ bdt_l)
{
    __shared__ __align__(16) float s_dt[2][SCH][32];
    __shared__ __align__(16) float s_x [2][SCH][32];
    __shared__ __align__(16) float s_z [2][SCH][32];
    __shared__ __align__(16) float s_db[2][SCH][52];   // full dbc row (48), padded
    __shared__ float s_wdt[16][33];                    // Wdt[r][d-local]

    const int b   = blockIdx.x >> 4;
    const int dg  = blockIdx.x & 15;
    const int d0  = dg * 32;
    const int tid = threadIdx.x;
    const int q   = tid & 3;
    const int dl  = tid >> 2;
    const int d   = d0 + dl;

    const int tl  = tid >> 3;       // 0..15 (time in chunk)
    const int seg = tid & 7;        // 0..7  (32-col segment *4)

    // dbc full-row loader mapping (192 float4 over 128 threads)
    const int r0 = tid / 12,        c0 = tid % 12;
    const int r1 = (tid + 128) / 12, c1 = (tid + 128) % 12;
    const bool ld1 = (tid < 64);

    // Wdt tile + per-thread bdt
    for (int i = tid; i < 16 * 32; i += 128)
        s_wdt[i >> 5][i & 31] = Wdt_l[(i >> 5) * DI + d0 + (i & 31)];
    float bdt4[4];
#pragma unroll
    for (int j = 0; j < 4; j++)
        bdt4[j] = bdt_l[d0 + seg * 4 + j];

    float a[4];
#pragma unroll
    for (int j = 0; j < 4; j++)
        a[j] = -__expf(A_log_l[d * NST + q * 4 + j]);
    const float dp = Dp_l[d];

    const size_t rb = (size_t)b * TT;

    float h0 = 0.f, h1 = 0.f, h2 = 0.f, h3 = 0.f;

    auto computeDt = [&](int bf) {
        float a0 = bdt4[0], a1 = bdt4[1], a2 = bdt4[2], a3 = bdt4[3];
#pragma unroll
        for (int r = 0; r < 16; r++) {
            float dbv = s_db[bf][tl][r];
            a0 += dbv * s_wdt[r][seg * 4 + 0];
            a1 += dbv * s_wdt[r][seg * 4 + 1];
            a2 += dbv * s_wdt[r][seg * 4 + 2];
            a3 += dbv * s_wdt[r][seg * 4 + 3];
        }
        s_dt[bf][tl][seg * 4 + 0] = (a0 > 20.f) ? a0 : log1pf(__expf(a0));
        s_dt[bf][tl][seg * 4 + 1] = (a1 > 20.f) ? a1 : log1pf(__expf(a1));
        s_dt[bf][tl][seg * 4 + 2] = (a2 > 20.f) ? a2 : log1pf(__expf(a2));
        s_dt[bf][tl][seg * 4 + 3] = (a3 > 20.f) ? a3 : log1pf(__expf(a3));
    };

    // prologue: chunk 0
    {
        size_t row = rb + tl;
        *(float4*)&s_x [0][tl][seg * 4] = *(const float4*)&g_xc [row * DI + d0 + seg * 4];
        *(float4*)&s_z [0][tl][seg * 4] = *(const float4*)&g_xz [row * (2 * DI) + DI + d0 + seg * 4];
        *(float4*)&s_db[0][r0][c0 * 4]  = *(const float4*)&g_dbc[(rb + r0) * DBCN + c0 * 4];
        if (ld1)
            *(float4*)&s_db[0][r1][c1 * 4] = *(const float4*)&g_dbc[(rb + r1) * DBCN + c1 * 4];
    }
    __syncthreads();
    computeDt(0);
    __syncthreads();

    int buf = 0;
    const int NC = TT / SCH;
    for (int c = 0; c < NC; c++) {
        // prefetch next chunk into registers
        float4 vx, vz, vdb0, vdb1;
        const bool more = (c + 1 < NC);
        if (more) {
            size_t cro = rb + (size_t)(c + 1) * SCH;
            size_t row = cro + tl;
            vx   = *(const float4*)&g_xc [row * DI + d0 + seg * 4];
            vz   = *(const float4*)&g_xz [row * (2 * DI) + DI + d0 + seg * 4];
            vdb0 = *(const float4*)&g_dbc[(cro + r0) * DBCN + c0 * 4];
            if (ld1)
                vdb1 = *(const float4*)&g_dbc[(cro + r1) * DBCN + c1 * 4];
        }

        // sequential compute over chunk c
#pragma unroll
        for (int it = 0; it < SCH; it++) {
            float dt  = s_dt[buf][it][dl];
            float x   = s_x [buf][it][dl];
            float4 Bv = *(const float4*)&s_db[buf][it][RR + q * 4];
            float4 Cv = *(const float4*)&s_db[buf][it][RR + NST + q * 4];
            float z   = s_z [buf][it][dl];

            float dtx = dt * x;
            h0 = __expf(dt * a[0]) * h0 + dtx * Bv.x;
            h1 = __expf(dt * a[1]) * h1 + dtx * Bv.y;
            h2 = __expf(dt * a[2]) * h2 + dtx * Bv.z;
            h3 = __expf(dt * a[3]) * h3 + dtx * Bv.w;

            float pv = h0 * Cv.x + h1 * Cv.y + h2 * Cv.z + h3 * Cv.w;
            pv += __shfl_xor_sync(0xffffffffu, pv, 1);
            pv += __shfl_xor_sync(0xffffffffu, pv, 2);

            if (q == 0) {
                float sz = __fdividef(z, 1.f + __expf(-z));
                size_t row = rb + (size_t)c * SCH + it;
                g_y[row * DI + d] = wmma::__float_to_tf32((pv + dp * x) * sz);
            }
        }

        if (more) {
            *(float4*)&s_x [buf ^ 1][tl][seg * 4] = vx;
            *(float4*)&s_z [buf ^ 1][tl][seg * 4] = vz;
            *(float4*)&s_db[buf ^ 1][r0][c0 * 4]  = vdb0;
            if (ld1)
                *(float4*)&s_db[buf ^ 1][r1][c1 * 4] = vdb1;
            __syncthreads();
            computeDt(buf ^ 1);
            __syncthreads();
        }
        buf ^= 1;
    }
}

// ---------------------------------------------------------------------------
// Mean over T (two-stage) + out-projection
// ---------------------------------------------------------------------------
__global__ void mean_part()
{
    int b = blockIdx.x >> 5;
    int c = blockIdx.x & 31;
    int col = threadIdx.x;   // 256

    const float* hp = g_h + ((size_t)b * TT + (size_t)c * 64) * DM + col;
    float s = 0.f;
#pragma unroll 8
    for (int t = 0; t < 64; t++)
        s += hp[(size_t)t * DM];
    g_part[(b * 32 + c) * DM + col] = s;
}

__global__ void mean_proj2(const float* __restrict__ Wop,
                           const float* __restrict__ bop,
                           float* __restrict__ out)
{
    __shared__ float hm[DM];
    int b = blockIdx.x;
    int c = threadIdx.x;

    float s = 0.f;
#pragma unroll
    for (int i = 0; i < 32; i++)
        s += g_part[(b * 32 + i) * DM + c];
    hm[c] = s * (1.f / (float)TT);
    __syncthreads();

    if (c < DOUT) {
        float acc = bop[c];
#pragma unroll 4
        for (int k = 0; k < DM; k++)
            acc += hm[k] * Wop[k * DOUT + c];
        out[b * DOUT + c] = acc;
    }
}

// ---------------------------------------------------------------------------
// Orchestration
// ---------------------------------------------------------------------------
static constexpr int SMEM_T(int BN)
{
    return 4 * (128 * 20 + 16 * (BN + 4)) * 4;
}

extern "C" void kernel_launch(void* const* d_in, const int* in_sizes, int n_in,
                              void* d_out, int out_size)
{
    const float* x        = (const float*)d_in[0];
    const float* W_in     = (const float*)d_in[1];
    const float* b_in     = (const float*)d_in[2];
    const float* Win      = (const float*)d_in[3];
    const float* bin_     = (const float*)d_in[4];
    const float* conv_w   = (const float*)d_in[5];
    const float* conv_b   = (const float*)d_in[6];
    const float* Wx       = (const float*)d_in[7];
    const float* Wdt      = (const float*)d_in[8];
    const float* bdt      = (const float*)d_in[9];
    const float* A_log    = (const float*)d_in[10];
    const float* Dp       = (const float*)d_in[11];
    const float* Wout     = (const float*)d_in[12];
    const float* W_op     = (const float*)d_in[13];
    const float* b_op     = (const float*)d_in[14];
    float* out = (float*)d_out;

    float *hbuf, *xzbuf, *xcbuf, *dbcbuf, *ybuf, *wt, *xtf;
    cudaGetSymbolAddress((void**)&hbuf,   g_h);
    cudaGetSymbolAddress((void**)&xzbuf,  g_xz);
    cudaGetSymbolAddress((void**)&xcbuf,  g_xc);
    cudaGetSymbolAddress((void**)&dbcbuf, g_dbc);
    cudaGetSymbolAddress((void**)&ybuf,   g_y);
    cudaGetSymbolAddress((void**)&wt,     g_wt);
    cudaGetSymbolAddress((void**)&xtf,    g_xtf);

    constexpr int SM128 = SMEM_T(128);
    constexpr int SM48  = SMEM_T(48);
    cudaFuncSetAttribute(tgemm<128, 4>, cudaFuncAttributeMaxDynamicSharedMemorySize, SM128);
    cudaFuncSetAttribute(tgemm<48, 8>,  cudaFuncAttributeMaxDynamicSharedMemorySize, SM48);

    // --- launch 1: batched tf32 truncation of all GEMM operands ---
    {
        CvtJobs jobs;
        jobs.j[0] = { x,    xtf,           ROWS * DIN        };
        jobs.j[1] = { W_in, wt + W_IN_OFF, DIN * DM          };
        jobs.j[2] = { Win,  wt + WIN_OFF,  LAY * DM * 2 * DI };
        jobs.j[3] = { Wx,   wt + WX_OFF,   LAY * DI * DBCN   };
        jobs.j[4] = { Wout, wt + WOUT_OFF, LAY * DI * DM     };
        int total = 0;
        for (int k = 0; k < 5; k++) total += jobs.j[k].n;
        tf32_cvt_multi<<<(total + 255) / 256, 256>>>(jobs, total);
    }

    const int EW_BLOCKS = (ROWS * DI + 255) / 256;

    // launch 2: in_proj
    {
        dim3 g(DM / 128, ROWS / 128);
        tgemm<128, 4><<<g, 256, SM128>>>(xtf, wt + W_IN_OFF, b_in, hbuf,
                                         ROWS, DM, DIN, 1);
    }

    for (int l = 0; l < LAY; l++) {
        const float* Win_l  = wt + WIN_OFF  + (size_t)l * DM * 2 * DI;
        const float* bin_l  = bin_   + (size_t)l * 2 * DI;
        const float* cw_l   = conv_w + (size_t)l * DI * 4;
        const float* cb_l   = conv_b + (size_t)l * DI;
        const float* Wx_l   = wt + WX_OFF   + (size_t)l * DI * DBCN;
        const float* Wdt_l  = Wdt    + (size_t)l * RR * DI;
        const float* bdt_l  = bdt    + (size_t)l * DI;
        const float* Alog_l = A_log  + (size_t)l * DI * NST;
        const float* Dp_l   = Dp     + (size_t)l * DI;
        const float* Wout_l = wt + WOUT_OFF + (size_t)l * DI * DM;

        // xz = h @ Win + bin
        {
            dim3 g((2 * DI) / 128, ROWS / 128);
            tgemm<128, 4><<<g, 256, SM128>>>(hbuf, Win_l, bin_l, xzbuf,
                                             ROWS, 2 * DI, DM, 0);
        }
        // xc
        conv_silu<<<EW_BLOCKS, 256>>>(cw_l, cb_l);
        // dbc = xc @ Wx
        {
            dim3 g(1, ROWS / 128);
            tgemm<48, 8><<<g, 256, SM48>>>(xcbuf, Wx_l, nullptr, dbcbuf,
                                           ROWS, DBCN, DI, 0);
        }
        // scan (+dt softplus +gating), launch #6 on first layer -> profiled
        ssm_scan_fused<<<BB * (DI / 32), 128>>>(Alog_l, Dp_l, Wdt_l, bdt_l);
        // h = y @ Wout
        {
            dim3 g(DM / 128, ROWS / 128);
            tgemm<128, 4><<<g, 256, SM128>>>(ybuf, Wout_l, nullptr, hbuf,
                                             ROWS, DM, DI, 1);
        }
    }

    mean_part<<<BB * 32, DM>>>();
    mean_proj2<<<BB, DM>>>(W_op, b_op, out);
}